// round 7
// baseline (speedup 1.0000x reference)
#include <cuda_runtime.h>
#include <cuda_bf16.h>
#include <cstdint>
#include <math.h>

// ---------------- device scratch (allocation-free) ----------------
__device__ __align__(16) __nv_bfloat16 g_xhi[256 * 1024];
__device__ __align__(16) __nv_bfloat16 g_xlo[256 * 1024];
__device__ __align__(16) __nv_bfloat16 g_Whi[512 * 1024];
__device__ __align__(16) __nv_bfloat16 g_Wlo[512 * 1024];
__device__ __align__(16) __nv_bfloat16 g_ub [512 * 1024];   // bf16(expm1(u[k][n])), layout [k][n]
__device__ __align__(16) __nv_bfloat16 g_Ebf[256 * 512];    // bf16(E)
__device__ float g_rs[16 * 256];                            // per-(ntile,row) fp32 rowsums of E

// ---------------- helpers ----------------
__device__ __forceinline__ uint32_t smem_u32(const void* p) {
    uint32_t a;
    asm("{ .reg .u64 t; cvta.to.shared.u64 t, %1; cvt.u32.u64 %0, t; }" : "=r"(a) : "l"(p));
    return a;
}
__device__ __forceinline__ void cp16(uint32_t dst, const void* src) {
    asm volatile("cp.async.cg.shared.global [%0], [%1], 16;" :: "r"(dst), "l"(src) : "memory");
}
#define CP_COMMIT() asm volatile("cp.async.commit_group;" ::: "memory")
#define CP_WAIT2()  asm volatile("cp.async.wait_group 2;" ::: "memory")

__device__ __forceinline__ void ldsm4(uint32_t* r, uint32_t addr) {
    asm volatile("ldmatrix.sync.aligned.m8n8.x4.shared.b16 {%0,%1,%2,%3}, [%4];"
        : "=r"(r[0]), "=r"(r[1]), "=r"(r[2]), "=r"(r[3]) : "r"(addr));
}
__device__ __forceinline__ void ldsm4t(uint32_t* r, uint32_t addr) {
    asm volatile("ldmatrix.sync.aligned.m8n8.x4.trans.shared.b16 {%0,%1,%2,%3}, [%4];"
        : "=r"(r[0]), "=r"(r[1]), "=r"(r[2]), "=r"(r[3]) : "r"(addr));
}
__device__ __forceinline__ void mma_bf16(float* c, const uint32_t* a, uint32_t b0, uint32_t b1) {
    asm volatile("mma.sync.aligned.m16n8k16.row.col.f32.bf16.bf16.f32 "
        "{%0,%1,%2,%3}, {%4,%5,%6,%7}, {%8,%9}, {%0,%1,%2,%3};"
        : "+f"(c[0]), "+f"(c[1]), "+f"(c[2]), "+f"(c[3])
        : "r"(a[0]), "r"(a[1]), "r"(a[2]), "r"(a[3]), "r"(b0), "r"(b1));
}

// split one float4 into bf16-hi uint2 and bf16-lo (residual) uint2
__device__ __forceinline__ void split4(float4 v, uint2& hi, uint2& lo) {
    __nv_bfloat16 h0 = __float2bfloat16(v.x), h1 = __float2bfloat16(v.y);
    __nv_bfloat16 h2 = __float2bfloat16(v.z), h3 = __float2bfloat16(v.w);
    __nv_bfloat162 hp0{h0, h1}, hp1{h2, h3};
    __nv_bfloat162 lp0{__float2bfloat16(v.x - __bfloat162float(h0)),
                       __float2bfloat16(v.y - __bfloat162float(h1))};
    __nv_bfloat162 lp1{__float2bfloat16(v.z - __bfloat162float(h2)),
                       __float2bfloat16(v.w - __bfloat162float(h3))};
    hi = make_uint2(*(uint32_t*)&hp0, *(uint32_t*)&hp1);
    lo = make_uint2(*(uint32_t*)&lp0, *(uint32_t*)&lp1);
}

// expm1 for u in [0,1e-3]: u*(1 + u*(1/2 + u/6)); 3 FFMA, no MUFU
__device__ __forceinline__ float expm1_small(float u) {
    return u * fmaf(u, fmaf(u, 0.16666667f, 0.5f), 1.0f);
}
__device__ __forceinline__ uint32_t poly_pack2(float a, float b) {
    __nv_bfloat162 v = __floats2bfloat162_rn(expm1_small(a), expm1_small(b));
    return *(uint32_t*)&v;
}

// ============================================================
// prep: bf16 hi/lo of x and W; g_ub = bf16(expm1(u)) in [k][n] layout.
// blocks: [0,64) x, [64,192) W, [192,320) u. 4 float4/thread, MLP=4.
// ============================================================
__global__ __launch_bounds__(256) void prep_kernel(
    const float* __restrict__ x, const float* __restrict__ W, const float* __restrict__ u)
{
    const int b = blockIdx.x, t = threadIdx.x;
    if (b < 192) {
        const float4* src;
        __nv_bfloat16 *dhi, *dlo;
        int base;
        if (b < 64) { src = (const float4*)x; dhi = g_xhi; dlo = g_xlo; base = b * 1024; }
        else        { src = (const float4*)W; dhi = g_Whi; dlo = g_Wlo; base = (b - 64) * 1024; }
        float4 v0 = src[base + 0 * 256 + t];
        float4 v1 = src[base + 1 * 256 + t];
        float4 v2 = src[base + 2 * 256 + t];
        float4 v3 = src[base + 3 * 256 + t];
        uint2 hi, lo;
        split4(v0, hi, lo); *(uint2*)&dhi[(base + 0*256 + t)*4] = hi; *(uint2*)&dlo[(base + 0*256 + t)*4] = lo;
        split4(v1, hi, lo); *(uint2*)&dhi[(base + 1*256 + t)*4] = hi; *(uint2*)&dlo[(base + 1*256 + t)*4] = lo;
        split4(v2, hi, lo); *(uint2*)&dhi[(base + 2*256 + t)*4] = hi; *(uint2*)&dlo[(base + 2*256 + t)*4] = lo;
        split4(v3, hi, lo); *(uint2*)&dhi[(base + 3*256 + t)*4] = hi; *(uint2*)&dlo[(base + 3*256 + t)*4] = lo;
    } else {
        const float4* src = (const float4*)u;
        int base = (b - 192) * 1024;
        float4 v0 = src[base + 0 * 256 + t];
        float4 v1 = src[base + 1 * 256 + t];
        float4 v2 = src[base + 2 * 256 + t];
        float4 v3 = src[base + 3 * 256 + t];
        *(uint2*)&g_ub[(base + 0*256 + t)*4] = make_uint2(poly_pack2(v0.x, v0.y), poly_pack2(v0.z, v0.w));
        *(uint2*)&g_ub[(base + 1*256 + t)*4] = make_uint2(poly_pack2(v1.x, v1.y), poly_pack2(v1.z, v1.w));
        *(uint2*)&g_ub[(base + 2*256 + t)*4] = make_uint2(poly_pack2(v2.x, v2.y), poly_pack2(v2.z, v2.w));
        *(uint2*)&g_ub[(base + 3*256 + t)*4] = make_uint2(poly_pack2(v3.x, v3.y), poly_pack2(v3.z, v3.w));
    }
}

// ============================================================
// GEMM1: E = exp(x @ W^T), bf16x3, 4-stage cp.async pipeline
// tile 32Mx32N, K=1024 in 16 chunks of 64; 256 thr / 8 warps (2x2 space, 2 k-split)
// grid 128 = 16 ntiles x 8 mtiles. dyn smem: 4 stages x 4 tiles x 32x72 bf16
// ============================================================
constexpr int P1    = 72;
constexpr int T1E   = 32 * P1;           // tile elems
constexpr int STG1E = 4 * T1E;           // stage elems (Ahi|Alo|Bhi|Blo)
constexpr int G1_DSMEM = 4 * STG1E * 2;  // 73728 B

__global__ __launch_bounds__(256) void gemm1_kernel()
{
    extern __shared__ __nv_bfloat16 sm[];
    __shared__ float sred[4][32][8];
    __shared__ float srs[2][32];

    const int tid = threadIdx.x, lane = tid & 31, wid = tid >> 5;
    const int nt = blockIdx.x & 15;
    const int m0 = (blockIdx.x >> 4) * 32, n0 = nt * 32;
    const uint32_t sb = smem_u32(sm);

    // loader: 4 tiles x 64 threads; each thread 4 consecutive 16B segs of one row-half
    const int tileid = tid >> 6, local = tid & 63;
    const int rowL = local >> 1, segq = (local & 1) * 4;
    const __nv_bfloat16* gsrc =
        (tileid == 0 ? g_xhi + m0 * 1024 :
         tileid == 1 ? g_xlo + m0 * 1024 :
         tileid == 2 ? g_Whi + n0 * 1024 : g_Wlo + n0 * 1024)
        + rowL * 1024 + segq * 8;
    const uint32_t sdst = sb + (uint32_t)((tileid * T1E + rowL * P1 + segq * 8) * 2);

    #define G1_ISSUE(c) do { \
        const uint32_t _d = sdst + ((c) & 3) * (STG1E * 2); \
        const __nv_bfloat16* _s = gsrc + (c) * 64; \
        cp16(_d,      _s);      cp16(_d + 16, _s + 8); \
        cp16(_d + 32, _s + 16); cp16(_d + 48, _s + 24); \
        CP_COMMIT(); \
    } while (0)

    // compute mapping
    const int wn = wid & 1, wm = (wid >> 1) & 1, wk = wid >> 2;
    const int lrow = lane & 15;
    const int lk = (lane >> 4) << 3;
    const uint32_t aOff = (uint32_t)(((wm * 16 + lrow) * P1 + lk) * 2);
    const uint32_t bOff = (uint32_t)(((wn * 16 + lrow) * P1 + lk) * 2);

    float hh0[4] = {}, hh1[4] = {}, hl0[4] = {}, hl1[4] = {}, lh0[4] = {}, lh1[4] = {};

    G1_ISSUE(0); G1_ISSUE(1); G1_ISSUE(2);

    for (int c = 0; c < 16; c++) {
        CP_WAIT2();
        __syncthreads();
        if (c + 3 < 16) G1_ISSUE(c + 3);
        const uint32_t st = sb + (c & 3) * (STG1E * 2);
        #pragma unroll
        for (int j = 0; j < 2; j++) {
            const int ks = wk * 2 + j;
            uint32_t a_hi[4], a_lo[4], b_hi[4], b_lo[4];
            ldsm4(a_hi, st + aOff + ks * 32);
            ldsm4(a_lo, st + T1E * 2 + aOff + ks * 32);
            ldsm4(b_hi, st + 2 * T1E * 2 + bOff + ks * 32);
            ldsm4(b_lo, st + 3 * T1E * 2 + bOff + ks * 32);
            mma_bf16(hh0, a_hi, b_hi[0], b_hi[2]);
            mma_bf16(hh1, a_hi, b_hi[1], b_hi[3]);
            mma_bf16(hl0, a_hi, b_lo[0], b_lo[2]);
            mma_bf16(hl1, a_hi, b_lo[1], b_lo[3]);
            mma_bf16(lh0, a_lo, b_hi[0], b_hi[2]);
            mma_bf16(lh1, a_lo, b_hi[1], b_hi[3]);
        }
    }
    #undef G1_ISSUE

    float acc0[4], acc1[4];
    #pragma unroll
    for (int i = 0; i < 4; i++) {
        acc0[i] = hh0[i] + hl0[i] + lh0[i];
        acc1[i] = hh1[i] + hl1[i] + lh1[i];
    }

    // k-split reduction: wk=0 warps absorb wk=1 partials
    if (wk == 1) {
        #pragma unroll
        for (int i = 0; i < 4; i++) {
            sred[wid - 4][lane][i]     = acc0[i];
            sred[wid - 4][lane][4 + i] = acc1[i];
        }
    }
    __syncthreads();

    if (wk == 0) {
        #pragma unroll
        for (int i = 0; i < 4; i++) {
            acc0[i] += sred[wid][lane][i];
            acc1[i] += sred[wid][lane][4 + i];
        }
        const int qr = lane >> 2;
        const int qc = (lane & 3) * 2;
        const int mrow0 = m0 + wm * 16 + qr;
        const int mrow1 = mrow0 + 8;
        float p0 = 0.f, p1 = 0.f;
        #pragma unroll
        for (int g = 0; g < 2; g++) {
            float* acc = g ? acc1 : acc0;
            float e0 = expf(acc[0]), e1 = expf(acc[1]);
            float e2 = expf(acc[2]), e3 = expf(acc[3]);
            p0 += e0 + e1; p1 += e2 + e3;
            const int n = n0 + wn * 16 + g * 8 + qc;
            __nv_bfloat162 v0 = __floats2bfloat162_rn(e0, e1);
            __nv_bfloat162 v1 = __floats2bfloat162_rn(e2, e3);
            *(uint32_t*)&g_Ebf[mrow0 * 512 + n] = *(uint32_t*)&v0;
            *(uint32_t*)&g_Ebf[mrow1 * 512 + n] = *(uint32_t*)&v1;
        }
        p0 += __shfl_xor_sync(0xFFFFFFFFu, p0, 1);
        p0 += __shfl_xor_sync(0xFFFFFFFFu, p0, 2);
        p1 += __shfl_xor_sync(0xFFFFFFFFu, p1, 1);
        p1 += __shfl_xor_sync(0xFFFFFFFFu, p1, 2);
        if ((lane & 3) == 0) {
            srs[wn][wm * 16 + qr]     = p0;
            srs[wn][wm * 16 + qr + 8] = p1;
        }
    }
    __syncthreads();
    if (tid < 32) g_rs[nt * 256 + m0 + tid] = srs[0][tid] + srs[1][tid];
}

// ============================================================
// GEMM2: y = E_bf16 @ g_ub + rowsum(E) + 512
// tile 32Mx64N, K=512 in 8 chunks of 64; B via ldmatrix.trans (g_ub is [k][n]).
// 256 thr / 8 warps (wn x wm x 2 k-split); 4-stage cp.async.
// grid 128 = 16 ntiles x 8 mtiles. dyn smem: 4 x (32x72 + 64x72) bf16
// ============================================================
constexpr int P2    = 72;
constexpr int ET2E  = 32 * P2;
constexpr int UT2E  = 64 * P2;
constexpr int STG2E = ET2E + UT2E;
constexpr int G2_DSMEM = 4 * STG2E * 2;  // 55296 B

__global__ __launch_bounds__(256) void gemm2_kernel(float* __restrict__ Y)
{
    extern __shared__ __nv_bfloat16 sm[];
    __shared__ float sred[4][32][16];
    __shared__ float rst[32];

    const int tid = threadIdx.x, lane = tid & 31, wid = tid >> 5;
    const int n0 = (blockIdx.x & 15) * 64;
    const int m0 = (blockIdx.x >> 4) * 32;
    const uint32_t sb = smem_u32(sm);

    if (tid < 32) {
        float s = 512.0f;
        #pragma unroll
        for (int j = 0; j < 16; j++) s += g_rs[j * 256 + m0 + tid];
        rst[tid] = s;
    }

    // loader: 3 cp16/thread: slot0 = E tile (32x8 segs), slots 1,2 = u tile (64x8 segs)
    const int rowA = tid >> 3, segA = tid & 7;
    const __nv_bfloat16* aSrc = g_Ebf + (m0 + rowA) * 512 + segA * 8;
    const uint32_t aDst = sb + (uint32_t)((rowA * P2 + segA * 8) * 2);
    const __nv_bfloat16* bSrc0 = g_ub + rowA * 1024 + n0 + segA * 8;           // k rows 0..31
    const uint32_t bDst0 = sb + (uint32_t)((ET2E + rowA * P2 + segA * 8) * 2);
    const __nv_bfloat16* bSrc1 = g_ub + (rowA + 32) * 1024 + n0 + segA * 8;    // k rows 32..63
    const uint32_t bDst1 = bDst0 + (uint32_t)(32 * P2 * 2);

    #define G2_ISSUE(c) do { \
        const uint32_t _so = ((c) & 3) * (STG2E * 2); \
        cp16(aDst + _so, aSrc + (c) * 64); \
        cp16(bDst0 + _so, bSrc0 + (c) * 64 * 1024); \
        cp16(bDst1 + _so, bSrc1 + (c) * 64 * 1024); \
        CP_COMMIT(); \
    } while (0)

    // compute mapping
    const int wn = wid & 1, wm = (wid >> 1) & 1, wk = wid >> 2;
    const int lrow = lane & 15;
    const int lk = (lane >> 4) << 3;
    const uint32_t aOff = (uint32_t)(((wm * 16 + lrow) * P2 + lk) * 2);
    const int li = lane & 7, kbit = (lane >> 3) & 1, nq = lane >> 4;
    const uint32_t tOff = (uint32_t)((((kbit * 8 + li) * P2) + nq * 8) * 2);

    float acc[4][4] = {};

    G2_ISSUE(0); G2_ISSUE(1); G2_ISSUE(2);

    for (int c = 0; c < 8; c++) {
        CP_WAIT2();
        __syncthreads();
        if (c + 3 < 8) G2_ISSUE(c + 3);
        const uint32_t st = sb + (c & 3) * (STG2E * 2);
        const uint32_t stU = st + ET2E * 2;
        #pragma unroll
        for (int j = 0; j < 2; j++) {
            const int ks = wk * 2 + j;
            uint32_t a[4], bq0[4], bq1[4];
            ldsm4(a, st + aOff + ks * 32);
            ldsm4t(bq0, stU + tOff + ks * 16 * P2 * 2 + (wn * 32 + 0) * 2);
            ldsm4t(bq1, stU + tOff + ks * 16 * P2 * 2 + (wn * 32 + 16) * 2);
            mma_bf16(acc[0], a, bq0[0], bq0[1]);
            mma_bf16(acc[1], a, bq0[2], bq0[3]);
            mma_bf16(acc[2], a, bq1[0], bq1[1]);
            mma_bf16(acc[3], a, bq1[2], bq1[3]);
        }
    }
    #undef G2_ISSUE

    if (wk == 1) {
        #pragma unroll
        for (int g = 0; g < 4; g++)
            #pragma unroll
            for (int i = 0; i < 4; i++)
                sred[wid - 4][lane][g * 4 + i] = acc[g][i];
    }
    __syncthreads();

    if (wk == 0) {
        #pragma unroll
        for (int g = 0; g < 4; g++)
            #pragma unroll
            for (int i = 0; i < 4; i++)
                acc[g][i] += sred[wid][lane][g * 4 + i];

        const int qr = lane >> 2;
        const int qc = (lane & 3) * 2;
        const int mrow0 = m0 + wm * 16 + qr;
        const int mrow1 = mrow0 + 8;
        const float r0v = rst[wm * 16 + qr];
        const float r1v = rst[wm * 16 + qr + 8];
        #pragma unroll
        for (int g = 0; g < 4; g++) {
            const int n = n0 + wn * 32 + g * 8 + qc;
            *(float2*)(Y + mrow0 * 1024 + n) = make_float2(acc[g][0] + r0v, acc[g][1] + r0v);
            *(float2*)(Y + mrow1 * 1024 + n) = make_float2(acc[g][2] + r1v, acc[g][3] + r1v);
        }
    }
}

// ============================================================
extern "C" void kernel_launch(void* const* d_in, const int* in_sizes, int n_in,
                              void* d_out, int out_size)
{
    const float* x = (const float*)d_in[0];   // 256 x 1024
    const float* W = (const float*)d_in[1];   // 512 x 1024
    const float* u = (const float*)d_in[2];   // 512 x 1024
    float* y = (float*)d_out;                 // 256 x 1024

    static bool attr_set = false;
    if (!attr_set) {
        cudaFuncSetAttribute(gemm1_kernel, cudaFuncAttributeMaxDynamicSharedMemorySize, G1_DSMEM);
        cudaFuncSetAttribute(gemm2_kernel, cudaFuncAttributeMaxDynamicSharedMemorySize, G2_DSMEM);
        attr_set = true;
    }

    prep_kernel<<<320, 256>>>(x, W, u);
    gemm1_kernel<<<128, 256, G1_DSMEM>>>();
    gemm2_kernel<<<128, 256, G2_DSMEM>>>(y);
}